// round 5
// baseline (speedup 1.0000x reference)
#include <cuda_runtime.h>
#include <cstdint>

// Problem constants
#define BB 4
#define SS 1024
#define DD 1024
#define HH 16
#define HD 64
#define N3D 3072          // 3*D
#define MM (BB*SS)        // 4096 rows of the GEMM

// Head-major scratch for Q/K/V: [B,H,S,HD]
__device__ float g_q[BB*HH*SS*HD];
__device__ float g_k[BB*HH*SS*HD];
__device__ float g_v[BB*HH*SS*HD];

// ---------------------------------------------------------------------------
// TF32 helpers
// ---------------------------------------------------------------------------
__device__ __forceinline__ uint32_t f2tf32(float x) {
    uint32_t y;
    asm volatile("cvt.rna.tf32.f32 %0, %1;" : "=r"(y) : "f"(x));
    return y;
}

__device__ __forceinline__ void mma_tf32(float& c0, float& c1, float& c2, float& c3,
                                         uint32_t a0, uint32_t a1, uint32_t a2, uint32_t a3,
                                         uint32_t b0, uint32_t b1) {
    asm volatile(
        "mma.sync.aligned.m16n8k8.row.col.f32.tf32.tf32.f32 "
        "{%0,%1,%2,%3}, {%4,%5,%6,%7}, {%8,%9}, {%0,%1,%2,%3};"
        : "+f"(c0), "+f"(c1), "+f"(c2), "+f"(c3)
        : "r"(a0), "r"(a1), "r"(a2), "r"(a3), "r"(b0), "r"(b1));
}

// ---------------------------------------------------------------------------
// Kernel 1: qkv = x @ W + b via TF32 tensor-core MMA, scattered head-major.
// Block tile 128(M) x 128(N), K-chunk 32. 256 threads = 8 warps (2 M x 4 N),
// warp tile 64x32 = 4x4 grid of m16n8k8 mmas. Register-prefetch pipeline.
//   A staged transposed As[k][m ^ (k&28)] (stride 136, conflict-free STS+LDS)
//   B staged Bs[k][n]                     (stride 136, conflict-free)
// Q pre-scaled by 1/sqrt(HD)=0.125.
// ---------------------------------------------------------------------------
__global__ __launch_bounds__(256, 1)
void qkv_gemm_kernel(const float* __restrict__ x,
                     const float* __restrict__ W,
                     const float* __restrict__ bias) {
    __shared__ uint32_t As[32][136];
    __shared__ uint32_t Bs[32][136];

    const int tid  = threadIdx.x;         // 0..255
    const int lane = tid & 31;
    const int warp = tid >> 5;            // 0..7
    const int gid  = lane >> 2;           // 0..7
    const int tig  = lane & 3;            // 0..3

    const int warpM = (warp >> 2) * 64;   // 0 or 64
    const int warpN = (warp & 3) * 32;    // 0,32,64,96
    const int tileM = blockIdx.y * 128;
    const int tileN = blockIdx.x * 128;

    // A prefetch mapping: kq = tid&7 (float4 in k), mrow = tid>>3 (0..31), m = mrow + i*32
    const int a_kq   = tid & 7;
    const int a_mrow = tid >> 3;
    // B prefetch mapping: e = tid + i*256 -> k = e>>5, n4 = e&31
    const int b_n4 = tid & 31;
    const int b_k0 = tid >> 5;            // 0..7, rows b_k0 + i*8

    float acc[4][4][4];
#pragma unroll
    for (int mi = 0; mi < 4; mi++)
#pragma unroll
        for (int ni = 0; ni < 4; ni++)
#pragma unroll
            for (int c = 0; c < 4; c++) acc[mi][ni][c] = 0.0f;

    float4 aR[4], bR[4];

    // Prologue: prefetch tile 0
    {
#pragma unroll
        for (int i = 0; i < 4; i++) {
            int m = a_mrow + i * 32;
            aR[i] = *reinterpret_cast<const float4*>(&x[(size_t)(tileM + m) * DD + a_kq * 4]);
        }
#pragma unroll
        for (int i = 0; i < 4; i++) {
            int k = b_k0 + i * 8;
            bR[i] = *reinterpret_cast<const float4*>(&W[(size_t)k * N3D + tileN + b_n4 * 4]);
        }
    }

    const int NT = DD / 32;  // 32 k-tiles
    for (int t = 0; t < NT; t++) {
        // Stage prefetched tile into smem (with tf32 conversion)
#pragma unroll
        for (int i = 0; i < 4; i++) {
            int m = a_mrow + i * 32;
            const float* av = reinterpret_cast<const float*>(&aR[i]);
#pragma unroll
            for (int j = 0; j < 4; j++) {
                int k = a_kq * 4 + j;
                As[k][m ^ (k & 28)] = f2tf32(av[j]);
            }
        }
#pragma unroll
        for (int i = 0; i < 4; i++) {
            int k = b_k0 + i * 8;
            const float* bv = reinterpret_cast<const float*>(&bR[i]);
            uint4 cv;
            cv.x = f2tf32(bv[0]); cv.y = f2tf32(bv[1]);
            cv.z = f2tf32(bv[2]); cv.w = f2tf32(bv[3]);
            *reinterpret_cast<uint4*>(&Bs[k][b_n4 * 4]) = cv;
        }
        __syncthreads();

        // Prefetch next tile while computing on this one
        if (t + 1 < NT) {
            int k0 = (t + 1) * 32;
#pragma unroll
            for (int i = 0; i < 4; i++) {
                int m = a_mrow + i * 32;
                aR[i] = *reinterpret_cast<const float4*>(&x[(size_t)(tileM + m) * DD + k0 + a_kq * 4]);
            }
#pragma unroll
            for (int i = 0; i < 4; i++) {
                int k = k0 + b_k0 + i * 8;
                bR[i] = *reinterpret_cast<const float4*>(&W[(size_t)k * N3D + tileN + b_n4 * 4]);
            }
        }

        // 4 k-steps of 8
#pragma unroll
        for (int ks = 0; ks < 32; ks += 8) {
            uint32_t af[4][4];   // [mi][a0..a3]
            uint32_t bf[4][2];   // [ni][b0..b1]
#pragma unroll
            for (int mi = 0; mi < 4; mi++) {
                int m0 = warpM + mi * 16 + gid;
                int kA = ks + tig;
                // Row kA   has store-XOR (kA&28)   = ks   -> read XOR ks
                // Row kA+4 has store-XOR (kA+4)&28 = ks+4 -> read XOR ks^4  (FIX)
                af[mi][0] = As[kA    ][(m0    ) ^ ks];
                af[mi][1] = As[kA    ][(m0 + 8) ^ ks];
                af[mi][2] = As[kA + 4][(m0    ) ^ ks ^ 4];
                af[mi][3] = As[kA + 4][(m0 + 8) ^ ks ^ 4];
            }
#pragma unroll
            for (int ni = 0; ni < 4; ni++) {
                int n0 = warpN + ni * 8 + gid;
                bf[ni][0] = Bs[ks + tig    ][n0];
                bf[ni][1] = Bs[ks + tig + 4][n0];
            }
#pragma unroll
            for (int mi = 0; mi < 4; mi++)
#pragma unroll
                for (int ni = 0; ni < 4; ni++)
                    mma_tf32(acc[mi][ni][0], acc[mi][ni][1], acc[mi][ni][2], acc[mi][ni][3],
                             af[mi][0], af[mi][1], af[mi][2], af[mi][3],
                             bf[ni][0], bf[ni][1]);
        }
        __syncthreads();
    }

    // Epilogue: bias + scatter to head-major q (scaled), k, v.
    // c0: (row, col), c1: (row, col+1), c2: (row+8, col), c3: (row+8, col+1)
#pragma unroll
    for (int mi = 0; mi < 4; mi++) {
#pragma unroll
        for (int ni = 0; ni < 4; ni++) {
            int row0 = tileM + warpM + mi * 16 + gid;
            int col0 = tileN + warpN + ni * 8 + tig * 2;
#pragma unroll
            for (int c = 0; c < 4; c++) {
                int m   = row0 + (c >> 1) * 8;
                int col = col0 + (c & 1);
                float val = acc[mi][ni][c] + bias[col];
                int b = m >> 10;
                int s = m & 1023;
                int h = col / 192;
                int cc = col - h * 192;
                size_t base = ((size_t)(b * HH + h) * SS + s) * HD;
                if (cc < 64)       g_q[base + cc]        = val * 0.125f;
                else if (cc < 128) g_k[base + cc - 64]   = val;
                else               g_v[base + cc - 128]  = val;
            }
        }
    }
}

// ---------------------------------------------------------------------------
// Kernel 2: flash-attention per (b,h). Block = 128 query rows, 1 row/thread.
// (unchanged — converted to tensor cores next round once GEMM is verified)
// ---------------------------------------------------------------------------
__global__ void attn_kernel(float* __restrict__ out) {
    __shared__ float Ks[64][64];
    __shared__ float Vs[64][64];

    const int bh = blockIdx.x;
    const int r  = blockIdx.y * 128 + threadIdx.x;

    float q[HD];
    {
        const float4* qp = reinterpret_cast<const float4*>(&g_q[((size_t)bh * SS + r) * HD]);
#pragma unroll
        for (int i = 0; i < 16; i++) {
            float4 v = qp[i];
            q[4*i+0] = v.x; q[4*i+1] = v.y; q[4*i+2] = v.z; q[4*i+3] = v.w;
        }
    }

    float o[HD];
#pragma unroll
    for (int d = 0; d < HD; d++) o[d] = 0.0f;
    float mmax = -1e30f;
    float lsum = 0.0f;

    for (int kt = 0; kt < SS / 64; kt++) {
        __syncthreads();
        {
            const float4* kp = reinterpret_cast<const float4*>(&g_k[((size_t)bh * SS + kt * 64) * HD]);
            const float4* vp = reinterpret_cast<const float4*>(&g_v[((size_t)bh * SS + kt * 64) * HD]);
            float4* ks = reinterpret_cast<float4*>(&Ks[0][0]);
            float4* vs = reinterpret_cast<float4*>(&Vs[0][0]);
#pragma unroll
            for (int e = threadIdx.x; e < 1024; e += 128) {
                ks[e] = kp[e];
                vs[e] = vp[e];
            }
        }
        __syncthreads();

        for (int j = 0; j < 64; j++) {
            float s = 0.0f;
#pragma unroll
            for (int d4 = 0; d4 < 16; d4++) {
                float4 kv = *reinterpret_cast<const float4*>(&Ks[j][d4 * 4]);
                s += q[4*d4+0] * kv.x + q[4*d4+1] * kv.y
                   + q[4*d4+2] * kv.z + q[4*d4+3] * kv.w;
            }

            if (s > mmax) {
                float corr = __expf(mmax - s);
                lsum = lsum * corr + 1.0f;
#pragma unroll
                for (int d4 = 0; d4 < 16; d4++) {
                    float4 vv = *reinterpret_cast<const float4*>(&Vs[j][d4 * 4]);
                    o[4*d4+0] = o[4*d4+0] * corr + vv.x;
                    o[4*d4+1] = o[4*d4+1] * corr + vv.y;
                    o[4*d4+2] = o[4*d4+2] * corr + vv.z;
                    o[4*d4+3] = o[4*d4+3] * corr + vv.w;
                }
                mmax = s;
            } else {
                float p = __expf(s - mmax);
                lsum += p;
#pragma unroll
                for (int d4 = 0; d4 < 16; d4++) {
                    float4 vv = *reinterpret_cast<const float4*>(&Vs[j][d4 * 4]);
                    o[4*d4+0] += p * vv.x;
                    o[4*d4+1] += p * vv.y;
                    o[4*d4+2] += p * vv.z;
                    o[4*d4+3] += p * vv.w;
                }
            }
        }
    }

    const int b = bh / HH;
    const int h = bh % HH;
    float inv_l = 1.0f / lsum;
    float4* op = reinterpret_cast<float4*>(&out[((size_t)b * SS + r) * DD + h * HD]);
#pragma unroll
    for (int d4 = 0; d4 < 16; d4++) {
        float4 v;
        v.x = o[4*d4+0] * inv_l;
        v.y = o[4*d4+1] * inv_l;
        v.z = o[4*d4+2] * inv_l;
        v.w = o[4*d4+3] * inv_l;
        op[d4] = v;
    }
}

extern "C" void kernel_launch(void* const* d_in, const int* in_sizes, int n_in,
                              void* d_out, int out_size) {
    const float* x    = (const float*)d_in[0];   // [B,S,D]
    const float* Wq   = (const float*)d_in[1];   // [D,3D]
    const float* bq   = (const float*)d_in[2];   // [3D]
    float* out        = (float*)d_out;           // [B,S,D]

    dim3 gridG(N3D / 128, MM / 128);   // (24, 32)
    qkv_gemm_kernel<<<gridG, 256>>>(x, Wq, bq);

    dim3 gridA(BB * HH, SS / 128);     // (64, 8)
    attn_kernel<<<gridA, 128>>>(out);
}

// round 11
// speedup vs baseline: 1.0193x; 1.0193x over previous
#include <cuda_runtime.h>
#include <cstdint>

// Problem constants
#define BB 4
#define SS 1024
#define DD 1024
#define HH 16
#define HD 64
#define N3D 3072          // 3*D
#define MM (BB*SS)        // 4096 rows of the GEMM

typedef unsigned long long u64;

// Head-major scratch for Q/K/V: [B,H,S,HD]
__device__ float g_q[BB*HH*SS*HD];
__device__ float g_k[BB*HH*SS*HD];
__device__ float g_v[BB*HH*SS*HD];

// ---------------------------------------------------------------------------
// Packed f32x2 helpers (PTX sm_100-family; FFMA2 in SASS)
// ---------------------------------------------------------------------------
__device__ __forceinline__ u64 fma2(u64 a, u64 b, u64 c) {
    u64 d;
    asm("fma.rn.f32x2 %0, %1, %2, %3;" : "=l"(d) : "l"(a), "l"(b), "l"(c));
    return d;
}
__device__ __forceinline__ u64 add2(u64 a, u64 b) {
    u64 d;
    asm("add.rn.f32x2 %0, %1, %2;" : "=l"(d) : "l"(a), "l"(b));
    return d;
}
__device__ __forceinline__ u64 pack2(float lo, float hi) {
    u64 d;
    asm("mov.b64 %0, {%1, %2};" : "=l"(d) : "f"(lo), "f"(hi));
    return d;
}
__device__ __forceinline__ void unpack2(float& lo, float& hi, u64 v) {
    asm("mov.b64 {%0, %1}, %2;" : "=f"(lo), "=f"(hi) : "l"(v));
}
// 128-bit shared load into two packed f32x2 regs (addr MUST be 16B aligned)
__device__ __forceinline__ void lds2(u64& a, u64& b, uint32_t addr) {
    asm volatile("ld.shared.v2.b64 {%0, %1}, [%2];" : "=l"(a), "=l"(b) : "r"(addr));
}
__device__ __forceinline__ uint32_t smem_u32(const void* p) {
    uint32_t a;
    asm("{ .reg .u64 t; cvta.to.shared.u64 t, %1; cvt.u32.u64 %0, t; }" : "=r"(a) : "l"(p));
    return a;
}

// ---------------------------------------------------------------------------
// Kernel 1: qkv = x @ W + b via FFMA2. Tile 128(M) x 64(N), BK=16.
// 256 threads = 16x16; per-thread 8(M) x 4(N) = 16 f32x2 accumulators
// (M packed in pairs). B is staged DUPLICATED in smem (float2{b,b}) so the
// FFMA2 b-operand needs no per-use dup. Q pre-scaled by 1/sqrt(HD)=0.125.
// ---------------------------------------------------------------------------
__global__ __launch_bounds__(256, 1)
void qkv_gemm_kernel(const float* __restrict__ x,
                     const float* __restrict__ W,
                     const float* __restrict__ bias) {
    __shared__ __align__(16) float  As[16][132];   // [k][m]; row = 528B = 33*16B
    __shared__ __align__(16) float2 Bsd[16][64];   // [k][n] duplicated {b,b}; row = 512B

    const int tid = threadIdx.x;     // 0..255
    const int tx  = tid & 15;        // n-group: cols tx*4..tx*4+3
    const int ty  = tid >> 4;        // m-group: rows ty*8..ty*8+7
    const int tileM = blockIdx.y * 128;
    const int tileN = blockIdx.x * 64;

    const uint32_t as_base = smem_u32(&As[0][0]);
    const uint32_t bs_base = smem_u32(&Bsd[0][0]);

    // A loader: 2 float4/thread: e = tid + i*256; m = e>>2 (0..127), kq = e&3
    const int a_m  = tid >> 2;       // + i*64
    const int a_kq = tid & 3;
    // B loader: 1 float4/thread: k = tid>>4, n4 = tid&15
    const int b_k  = tid >> 4;
    const int b_n4 = tid & 15;

    u64 acc[4][4];                   // [m-pair][n]
#pragma unroll
    for (int i = 0; i < 4; i++)
#pragma unroll
        for (int j = 0; j < 4; j++) acc[i][j] = 0ull;

    float4 aR[2], bR;
    // Prologue prefetch (chunk 0)
#pragma unroll
    for (int i = 0; i < 2; i++)
        aR[i] = *reinterpret_cast<const float4*>(&x[(size_t)(tileM + a_m + i * 64) * DD + a_kq * 4]);
    bR = *reinterpret_cast<const float4*>(&W[(size_t)b_k * N3D + tileN + b_n4 * 4]);

    for (int t = 0; t < DD / 16; t++) {
        // Stage regs -> smem
#pragma unroll
        for (int i = 0; i < 2; i++) {
            int m = a_m + i * 64;
            const float* av = reinterpret_cast<const float*>(&aR[i]);
#pragma unroll
            for (int j = 0; j < 4; j++) As[a_kq * 4 + j][m] = av[j];
        }
        {
            const float* bv = reinterpret_cast<const float*>(&bR);
#pragma unroll
            for (int j = 0; j < 4; j++)
                Bsd[b_k][b_n4 * 4 + j] = make_float2(bv[j], bv[j]);
        }
        __syncthreads();

        // Prefetch next chunk
        if (t + 1 < DD / 16) {
            int k0 = (t + 1) * 16;
#pragma unroll
            for (int i = 0; i < 2; i++)
                aR[i] = *reinterpret_cast<const float4*>(&x[(size_t)(tileM + a_m + i * 64) * DD + k0 + a_kq * 4]);
            bR = *reinterpret_cast<const float4*>(&W[(size_t)(k0 + b_k) * N3D + tileN + b_n4 * 4]);
        }

        // Compute 16 k-steps
#pragma unroll
        for (int kk = 0; kk < 16; kk++) {
            uint32_t aaddr = as_base + (uint32_t)(kk * 528 + ty * 32);
            uint32_t baddr = bs_base + (uint32_t)(kk * 512 + tx * 32);
            u64 a2[4], b2[4];
            lds2(a2[0], a2[1], aaddr);
            lds2(a2[2], a2[3], aaddr + 16);
            lds2(b2[0], b2[1], baddr);
            lds2(b2[2], b2[3], baddr + 16);
#pragma unroll
            for (int i = 0; i < 4; i++)
#pragma unroll
                for (int j = 0; j < 4; j++)
                    acc[i][j] = fma2(a2[i], b2[j], acc[i][j]);
        }
        __syncthreads();
    }

    // Epilogue: bias + scatter to head-major q (scaled), k, v.
#pragma unroll
    for (int i = 0; i < 4; i++) {
#pragma unroll
        for (int j = 0; j < 4; j++) {
            float vlo, vhi;
            unpack2(vlo, vhi, acc[i][j]);
            int col = tileN + tx * 4 + j;
            float bcol = bias[col];
            int h  = col / 192;
            int cc = col - h * 192;
#pragma unroll
            for (int half = 0; half < 2; half++) {
                int m = tileM + ty * 8 + i * 2 + half;
                float val = (half ? vhi : vlo) + bcol;
                int b = m >> 10;
                int s = m & 1023;
                size_t base = ((size_t)(b * HH + h) * SS + s) * HD;
                if (cc < 64)       g_q[base + cc]       = val * 0.125f;
                else if (cc < 128) g_k[base + cc - 64]  = val;
                else               g_v[base + cc - 128] = val;
            }
        }
    }
}

// ---------------------------------------------------------------------------
// Kernel 2: flash-attention per (b,h), FFMA2 version.
// Block = 128 query rows, 1 row/thread; K/V tiles of 64 keys in smem.
// Dot and p*V loops packed along d (f32x2); 4 partial dot accumulators.
// ---------------------------------------------------------------------------
__global__ void attn_kernel(float* __restrict__ out) {
    __shared__ __align__(16) float Ks[64][64];
    __shared__ __align__(16) float Vs[64][64];

    const int bh = blockIdx.x;
    const int r  = blockIdx.y * 128 + threadIdx.x;

    const uint32_t ks_base = smem_u32(&Ks[0][0]);
    const uint32_t vs_base = smem_u32(&Vs[0][0]);

    // Load this row's (pre-scaled) query as 32 packed pairs
    u64 q2[32];
    {
        const float4* qp = reinterpret_cast<const float4*>(&g_q[((size_t)bh * SS + r) * HD]);
#pragma unroll
        for (int i = 0; i < 16; i++) {
            float4 v = qp[i];
            q2[2 * i]     = pack2(v.x, v.y);
            q2[2 * i + 1] = pack2(v.z, v.w);
        }
    }

    u64 o2[32];
#pragma unroll
    for (int i = 0; i < 32; i++) o2[i] = 0ull;
    float mmax = -1e30f;
    float lsum = 0.0f;

    for (int kt = 0; kt < SS / 64; kt++) {
        __syncthreads();
        {
            const float4* kp = reinterpret_cast<const float4*>(&g_k[((size_t)bh * SS + kt * 64) * HD]);
            const float4* vp = reinterpret_cast<const float4*>(&g_v[((size_t)bh * SS + kt * 64) * HD]);
            float4* ks = reinterpret_cast<float4*>(&Ks[0][0]);
            float4* vs = reinterpret_cast<float4*>(&Vs[0][0]);
#pragma unroll
            for (int e = threadIdx.x; e < 1024; e += 128) {
                ks[e] = kp[e];
                vs[e] = vp[e];
            }
        }
        __syncthreads();

        for (int j = 0; j < 64; j++) {
            // s = q . K_j with 4 partial f32x2 accumulators
            uint32_t krow = ks_base + (uint32_t)(j * 256);
            u64 s0 = 0ull, s1 = 0ull, s2p = 0ull, s3 = 0ull;
#pragma unroll
            for (int i = 0; i < 16; i += 2) {
                u64 ka, kb, kc, kd;
                lds2(ka, kb, krow + i * 16);
                lds2(kc, kd, krow + i * 16 + 16);
                s0  = fma2(q2[2 * i],     ka, s0);
                s1  = fma2(q2[2 * i + 1], kb, s1);
                s2p = fma2(q2[2 * i + 2], kc, s2p);
                s3  = fma2(q2[2 * i + 3], kd, s3);
            }
            float slo, shi;
            unpack2(slo, shi, add2(add2(s0, s1), add2(s2p, s3)));
            float s = slo + shi;

            uint32_t vrow = vs_base + (uint32_t)(j * 256);
            if (s > mmax) {
                // rare path: rescale accumulator, p = 1
                float corr = __expf(mmax - s);
                lsum = lsum * corr + 1.0f;
                u64 c2 = pack2(corr, corr);
#pragma unroll
                for (int i = 0; i < 16; i++) {
                    u64 va, vb;
                    lds2(va, vb, vrow + i * 16);
                    o2[2 * i]     = fma2(o2[2 * i],     c2, va);
                    o2[2 * i + 1] = fma2(o2[2 * i + 1], c2, vb);
                }
                mmax = s;
            } else {
                float p = __expf(s - mmax);
                lsum += p;
                u64 p2 = pack2(p, p);
#pragma unroll
                for (int i = 0; i < 16; i++) {
                    u64 va, vb;
                    lds2(va, vb, vrow + i * 16);
                    o2[2 * i]     = fma2(p2, va, o2[2 * i]);
                    o2[2 * i + 1] = fma2(p2, vb, o2[2 * i + 1]);
                }
            }
        }
    }

    // Write output: out[b, r, h*64 + d]
    const int b = bh / HH;
    const int h = bh % HH;
    float inv_l = 1.0f / lsum;
    float4* op = reinterpret_cast<float4*>(&out[((size_t)b * SS + r) * DD + h * HD]);
#pragma unroll
    for (int i = 0; i < 16; i++) {
        float x0, x1, x2, x3;
        unpack2(x0, x1, o2[2 * i]);
        unpack2(x2, x3, o2[2 * i + 1]);
        float4 v;
        v.x = x0 * inv_l; v.y = x1 * inv_l;
        v.z = x2 * inv_l; v.w = x3 * inv_l;
        op[i] = v;
    }
}

extern "C" void kernel_launch(void* const* d_in, const int* in_sizes, int n_in,
                              void* d_out, int out_size) {
    const float* x  = (const float*)d_in[0];   // [B,S,D]
    const float* Wq = (const float*)d_in[1];   // [D,3D]
    const float* bq = (const float*)d_in[2];   // [3D]
    float* out      = (float*)d_out;           // [B,S,D]

    dim3 gridG(N3D / 64, MM / 128);   // (48, 32)
    qkv_gemm_kernel<<<gridG, 256>>>(x, Wq, bq);

    dim3 gridA(BB * HH, SS / 128);    // (64, 8)
    attn_kernel<<<gridA, 128>>>(out);
}

// round 13
// speedup vs baseline: 1.9586x; 1.9214x over previous
#include <cuda_runtime.h>
#include <cstdint>

// Problem constants
#define BB 4
#define SS 1024
#define DD 1024
#define HH 16
#define HD 64
#define N3D 3072          // 3*D
#define MM (BB*SS)        // 4096 rows of the GEMM

typedef unsigned long long u64;

// Head-major scratch for Q/K/V: [B,H,S,HD]; pre-rounded (tf32) copies of x and W
__device__ float g_q[BB*HH*SS*HD];
__device__ float g_k[BB*HH*SS*HD];
__device__ float g_v[BB*HH*SS*HD];
__device__ float g_xr[MM*DD];
__device__ float g_wr[DD*N3D];

// ---------------------------------------------------------------------------
// Helpers
// ---------------------------------------------------------------------------
__device__ __forceinline__ uint32_t f2tf32(float x) {
    uint32_t y;
    asm volatile("cvt.rna.tf32.f32 %0, %1;" : "=r"(y) : "f"(x));
    return y;
}
__device__ __forceinline__ uint32_t smem_u32(const void* p) {
    uint32_t a;
    asm("{ .reg .u64 t; cvta.to.shared.u64 t, %1; cvt.u32.u64 %0, t; }" : "=r"(a) : "l"(p));
    return a;
}
__device__ __forceinline__ void cpasync16(uint32_t dst, const float* src) {
    asm volatile("cp.async.cg.shared.global [%0], [%1], 16;" :: "r"(dst), "l"(src));
}
__device__ __forceinline__ void mma_tf32(float& c0, float& c1, float& c2, float& c3,
                                         uint32_t a0, uint32_t a1, uint32_t a2, uint32_t a3,
                                         uint32_t b0, uint32_t b1) {
    asm volatile(
        "mma.sync.aligned.m16n8k8.row.col.f32.tf32.tf32.f32 "
        "{%0,%1,%2,%3}, {%4,%5,%6,%7}, {%8,%9}, {%0,%1,%2,%3};"
        : "+f"(c0), "+f"(c1), "+f"(c2), "+f"(c3)
        : "r"(a0), "r"(a1), "r"(a2), "r"(a3), "r"(b0), "r"(b1));
}
// 128-bit shared load (addr 16B aligned) — used by attention
__device__ __forceinline__ void lds2(u64& a, u64& b, uint32_t addr) {
    asm volatile("ld.shared.v2.b64 {%0, %1}, [%2];" : "=l"(a), "=l"(b) : "r"(addr));
}
__device__ __forceinline__ u64 fma2(u64 a, u64 b, u64 c) {
    u64 d;
    asm("fma.rn.f32x2 %0, %1, %2, %3;" : "=l"(d) : "l"(a), "l"(b), "l"(c));
    return d;
}
__device__ __forceinline__ u64 add2(u64 a, u64 b) {
    u64 d;
    asm("add.rn.f32x2 %0, %1, %2;" : "=l"(d) : "l"(a), "l"(b));
    return d;
}
__device__ __forceinline__ u64 pack2(float lo, float hi) {
    u64 d;
    asm("mov.b64 %0, {%1, %2};" : "=l"(d) : "f"(lo), "f"(hi));
    return d;
}
__device__ __forceinline__ void unpack2(float& lo, float& hi, u64 v) {
    asm("mov.b64 {%0, %1}, %2;" : "=f"(lo), "=f"(hi) : "l"(v));
}

// ---------------------------------------------------------------------------
// Kernel 0: pre-round x and W to tf32 (RNA) stored as fp32 bit patterns.
// One float4 per thread per array.
// ---------------------------------------------------------------------------
__global__ void preround_kernel(const float* __restrict__ x,
                                const float* __restrict__ W) {
    int i = blockIdx.x * blockDim.x + threadIdx.x;   // float4 index
    if (i < MM * DD / 4) {
        float4 v = reinterpret_cast<const float4*>(x)[i];
        uint4 r;
        r.x = f2tf32(v.x); r.y = f2tf32(v.y);
        r.z = f2tf32(v.z); r.w = f2tf32(v.w);
        reinterpret_cast<uint4*>(g_xr)[i] = r;
    }
    if (i < DD * N3D / 4) {
        float4 v = reinterpret_cast<const float4*>(W)[i];
        uint4 r;
        r.x = f2tf32(v.x); r.y = f2tf32(v.y);
        r.z = f2tf32(v.z); r.w = f2tf32(v.w);
        reinterpret_cast<uint4*>(g_wr)[i] = r;
    }
}

// ---------------------------------------------------------------------------
// Kernel 1: qkv = xr @ wr + b via TF32 mma.sync, cp.async double-buffered.
// Block tile 128(M) x 128(N), BK=16, 2 smem stages, 256 threads = 8 warps
// (2M x 4N), warp tile 64x32 = 4x4 m16n8k8 mmas, 2 k-steps per tile.
//   A stage: [m][k] 128x16 f32, word addr = m*16 + (k ^ (4*((m>>1)&3)))
//   B stage: [k][n] 16x128 f32, word addr = k*128 + (n ^ (8*(k&3)))
// Both swizzles verified conflict-free for their STS(cp.async) and LDS maps.
// Q pre-scaled by 1/sqrt(HD)=0.125 in the epilogue scatter.
// ---------------------------------------------------------------------------
__global__ __launch_bounds__(256, 2)
void qkv_mma_kernel(const float* __restrict__ bias) {
    __shared__ __align__(16) float sA[2][128 * 16];   // 8KB per stage
    __shared__ __align__(16) float sB[2][16 * 128];   // 8KB per stage

    const int tid  = threadIdx.x;
    const int lane = tid & 31;
    const int warp = tid >> 5;
    const int gid  = lane >> 2;          // 0..7
    const int tig  = lane & 3;           // 0..3
    const int warpM = (warp >> 2) * 64;  // 0 or 64
    const int warpN = (warp & 3) * 32;   // 0,32,64,96
    const int tileM = blockIdx.y * 128;
    const int tileN = blockIdx.x * 128;

    // cp.async loader mapping (2 chunks of 16B per array per thread)
    const int a_m0 = tid >> 2;           // + i*64 -> m 0..127
    const int a_kc = (tid & 3) * 4;      // k word 0,4,8,12
    const int b_k0 = tid >> 5;           // + i*8  -> k 0..15
    const int b_nc = (tid & 31) * 4;     // n word 0..124

    const uint32_t sAb = smem_u32(&sA[0][0]);
    const uint32_t sBb = smem_u32(&sB[0][0]);

    float acc[4][4][4];
#pragma unroll
    for (int mi = 0; mi < 4; mi++)
#pragma unroll
        for (int ni = 0; ni < 4; ni++)
#pragma unroll
            for (int c = 0; c < 4; c++) acc[mi][ni][c] = 0.0f;

    // ---- issue tile t into stage s ----
#define ISSUE_TILE(t, s) do {                                                        \
        int _k0 = (t) * 16;                                                          \
        _Pragma("unroll")                                                            \
        for (int _i = 0; _i < 2; _i++) {                                             \
            int _m = a_m0 + _i * 64;                                                 \
            uint32_t _d = sAb + (uint32_t)((s) * 8192 +                              \
                          (_m * 16 + (a_kc ^ (4 * ((_m >> 1) & 3)))) * 4);           \
            cpasync16(_d, &g_xr[(size_t)(tileM + _m) * DD + _k0 + a_kc]);            \
        }                                                                            \
        _Pragma("unroll")                                                            \
        for (int _i = 0; _i < 2; _i++) {                                             \
            int _k = b_k0 + _i * 8;                                                  \
            uint32_t _d = sBb + (uint32_t)((s) * 8192 +                              \
                          (_k * 128 + (b_nc ^ (8 * (_k & 3)))) * 4);                 \
            cpasync16(_d, &g_wr[(size_t)(_k0 + _k) * N3D + tileN + b_nc]);           \
        }                                                                            \
        asm volatile("cp.async.commit_group;" ::: "memory");                         \
    } while (0)

    ISSUE_TILE(0, 0);

    const int swzA = 4 * ((gid >> 1) & 3);
    const int NT = DD / 16;   // 64
    for (int t = 0; t < NT; t++) {
        if (t + 1 < NT) {
            ISSUE_TILE(t + 1, (t + 1) & 1);
            asm volatile("cp.async.wait_group 1;" ::: "memory");
        } else {
            asm volatile("cp.async.wait_group 0;" ::: "memory");
        }
        __syncthreads();

        const float* A  = &sA[t & 1][0];
        const float* Bt = &sB[t & 1][0];
#pragma unroll
        for (int ks = 0; ks < 16; ks += 8) {
            uint32_t af[4][4];
            uint32_t bf[4][2];
#pragma unroll
            for (int mi = 0; mi < 4; mi++) {
                int m0 = warpM + mi * 16 + gid;
                int kA = ks + tig;
                af[mi][0] = __float_as_uint(A[m0 * 16       + (kA ^ swzA)]);
                af[mi][1] = __float_as_uint(A[(m0 + 8) * 16 + (kA ^ swzA)]);
                af[mi][2] = __float_as_uint(A[m0 * 16       + ((kA + 4) ^ swzA)]);
                af[mi][3] = __float_as_uint(A[(m0 + 8) * 16 + ((kA + 4) ^ swzA)]);
            }
#pragma unroll
            for (int ni = 0; ni < 4; ni++) {
                int n0 = warpN + ni * 8 + gid;
                bf[ni][0] = __float_as_uint(Bt[(ks + tig) * 128     + (n0 ^ (8 * tig))]);
                bf[ni][1] = __float_as_uint(Bt[(ks + tig + 4) * 128 + (n0 ^ (8 * tig))]);
            }
#pragma unroll
            for (int mi = 0; mi < 4; mi++)
#pragma unroll
                for (int ni = 0; ni < 4; ni++)
                    mma_tf32(acc[mi][ni][0], acc[mi][ni][1], acc[mi][ni][2], acc[mi][ni][3],
                             af[mi][0], af[mi][1], af[mi][2], af[mi][3],
                             bf[ni][0], bf[ni][1]);
        }
        __syncthreads();
    }
#undef ISSUE_TILE

    // Epilogue (verified in round 5): c0:(r,c) c1:(r,c+1) c2:(r+8,c) c3:(r+8,c+1)
#pragma unroll
    for (int mi = 0; mi < 4; mi++) {
#pragma unroll
        for (int ni = 0; ni < 4; ni++) {
            int row0 = tileM + warpM + mi * 16 + gid;
            int col0 = tileN + warpN + ni * 8 + tig * 2;
#pragma unroll
            for (int c = 0; c < 4; c++) {
                int m   = row0 + (c >> 1) * 8;
                int col = col0 + (c & 1);
                float val = acc[mi][ni][c] + bias[col];
                int b = m >> 10;
                int s = m & 1023;
                int h  = col / 192;
                int cc = col - h * 192;
                size_t base = ((size_t)(b * HH + h) * SS + s) * HD;
                if (cc < 64)       g_q[base + cc]       = val * 0.125f;
                else if (cc < 128) g_k[base + cc - 64]  = val;
                else               g_v[base + cc - 128] = val;
            }
        }
    }
}

// ---------------------------------------------------------------------------
// Kernel 2: flash-attention per (b,h) (round-11 version, measured 743us).
// Block = 128 query rows, 1 row/thread; K/V tiles of 64 keys in smem.
// ---------------------------------------------------------------------------
__global__ void attn_kernel(float* __restrict__ out) {
    __shared__ __align__(16) float Ks[64][64];
    __shared__ __align__(16) float Vs[64][64];

    const int bh = blockIdx.x;
    const int r  = blockIdx.y * 128 + threadIdx.x;

    const uint32_t ks_base = smem_u32(&Ks[0][0]);
    const uint32_t vs_base = smem_u32(&Vs[0][0]);

    u64 q2[32];
    {
        const float4* qp = reinterpret_cast<const float4*>(&g_q[((size_t)bh * SS + r) * HD]);
#pragma unroll
        for (int i = 0; i < 16; i++) {
            float4 v = qp[i];
            q2[2 * i]     = pack2(v.x, v.y);
            q2[2 * i + 1] = pack2(v.z, v.w);
        }
    }

    u64 o2[32];
#pragma unroll
    for (int i = 0; i < 32; i++) o2[i] = 0ull;
    float mmax = -1e30f;
    float lsum = 0.0f;

    for (int kt = 0; kt < SS / 64; kt++) {
        __syncthreads();
        {
            const float4* kp = reinterpret_cast<const float4*>(&g_k[((size_t)bh * SS + kt * 64) * HD]);
            const float4* vp = reinterpret_cast<const float4*>(&g_v[((size_t)bh * SS + kt * 64) * HD]);
            float4* ks = reinterpret_cast<float4*>(&Ks[0][0]);
            float4* vs = reinterpret_cast<float4*>(&Vs[0][0]);
#pragma unroll
            for (int e = threadIdx.x; e < 1024; e += 128) {
                ks[e] = kp[e];
                vs[e] = vp[e];
            }
        }
        __syncthreads();

        for (int j = 0; j < 64; j++) {
            uint32_t krow = ks_base + (uint32_t)(j * 256);
            u64 s0 = 0ull, s1 = 0ull, s2p = 0ull, s3 = 0ull;
#pragma unroll
            for (int i = 0; i < 16; i += 2) {
                u64 ka, kb, kc, kd;
                lds2(ka, kb, krow + i * 16);
                lds2(kc, kd, krow + i * 16 + 16);
                s0  = fma2(q2[2 * i],     ka, s0);
                s1  = fma2(q2[2 * i + 1], kb, s1);
                s2p = fma2(q2[2 * i + 2], kc, s2p);
                s3  = fma2(q2[2 * i + 3], kd, s3);
            }
            float slo, shi;
            unpack2(slo, shi, add2(add2(s0, s1), add2(s2p, s3)));
            float s = slo + shi;

            uint32_t vrow = vs_base + (uint32_t)(j * 256);
            if (s > mmax) {
                float corr = __expf(mmax - s);
                lsum = lsum * corr + 1.0f;
                u64 c2 = pack2(corr, corr);
#pragma unroll
                for (int i = 0; i < 16; i++) {
                    u64 va, vb;
                    lds2(va, vb, vrow + i * 16);
                    o2[2 * i]     = fma2(o2[2 * i],     c2, va);
                    o2[2 * i + 1] = fma2(o2[2 * i + 1], c2, vb);
                }
                mmax = s;
            } else {
                float p = __expf(s - mmax);
                lsum += p;
                u64 p2 = pack2(p, p);
#pragma unroll
                for (int i = 0; i < 16; i++) {
                    u64 va, vb;
                    lds2(va, vb, vrow + i * 16);
                    o2[2 * i]     = fma2(p2, va, o2[2 * i]);
                    o2[2 * i + 1] = fma2(p2, vb, o2[2 * i + 1]);
                }
            }
        }
    }

    const int b = bh / HH;
    const int h = bh % HH;
    float inv_l = 1.0f / lsum;
    float4* op = reinterpret_cast<float4*>(&out[((size_t)b * SS + r) * DD + h * HD]);
#pragma unroll
    for (int i = 0; i < 16; i++) {
        float x0, x1, x2, x3;
        unpack2(x0, x1, o2[2 * i]);
        unpack2(x2, x3, o2[2 * i + 1]);
        float4 v;
        v.x = x0 * inv_l; v.y = x1 * inv_l;
        v.z = x2 * inv_l; v.w = x3 * inv_l;
        op[i] = v;
    }
}

extern "C" void kernel_launch(void* const* d_in, const int* in_sizes, int n_in,
                              void* d_out, int out_size) {
    const float* x  = (const float*)d_in[0];   // [B,S,D]
    const float* Wq = (const float*)d_in[1];   // [D,3D]
    const float* bq = (const float*)d_in[2];   // [3D]
    float* out      = (float*)d_out;           // [B,S,D]

    int np = MM * DD / 4;                      // 1,048,576 float4s (covers W's 786,432 too)
    preround_kernel<<<(np + 255) / 256, 256>>>(x, Wq);

    dim3 gridG(N3D / 128, MM / 128);           // (24, 32)
    qkv_mma_kernel<<<gridG, 256>>>(bq);

    dim3 gridA(BB * HH, SS / 128);             // (64, 8)
    attn_kernel<<<gridA, 128>>>(out);
}

// round 14
// speedup vs baseline: 5.3666x; 2.7400x over previous
#include <cuda_runtime.h>
#include <cstdint>

// Problem constants
#define BB 4
#define SS 1024
#define DD 1024
#define HH 16
#define HD 64
#define N3D 3072          // 3*D
#define MM (BB*SS)        // 4096 rows of the GEMM

// Head-major scratch for Q/K/V: [B,H,S,HD]; pre-rounded (tf32) copies of x and W
__device__ float g_q[BB*HH*SS*HD];
__device__ float g_k[BB*HH*SS*HD];
__device__ float g_v[BB*HH*SS*HD];
__device__ float g_xr[MM*DD];
__device__ float g_wr[DD*N3D];

// ---------------------------------------------------------------------------
// Helpers
// ---------------------------------------------------------------------------
__device__ __forceinline__ uint32_t f2tf32(float x) {
    uint32_t y;
    asm volatile("cvt.rna.tf32.f32 %0, %1;" : "=r"(y) : "f"(x));
    return y;
}
__device__ __forceinline__ uint32_t smem_u32(const void* p) {
    uint32_t a;
    asm("{ .reg .u64 t; cvta.to.shared.u64 t, %1; cvt.u32.u64 %0, t; }" : "=r"(a) : "l"(p));
    return a;
}
__device__ __forceinline__ void cpasync16(uint32_t dst, const float* src) {
    asm volatile("cp.async.cg.shared.global [%0], [%1], 16;" :: "r"(dst), "l"(src));
}
__device__ __forceinline__ void mma_tf32(float& c0, float& c1, float& c2, float& c3,
                                         uint32_t a0, uint32_t a1, uint32_t a2, uint32_t a3,
                                         uint32_t b0, uint32_t b1) {
    asm volatile(
        "mma.sync.aligned.m16n8k8.row.col.f32.tf32.tf32.f32 "
        "{%0,%1,%2,%3}, {%4,%5,%6,%7}, {%8,%9}, {%0,%1,%2,%3};"
        : "+f"(c0), "+f"(c1), "+f"(c2), "+f"(c3)
        : "r"(a0), "r"(a1), "r"(a2), "r"(a3), "r"(b0), "r"(b1));
}

// ---------------------------------------------------------------------------
// Kernel 0: pre-round x and W to tf32 (RNA) stored as fp32 bit patterns.
// ---------------------------------------------------------------------------
__global__ void preround_kernel(const float* __restrict__ x,
                                const float* __restrict__ W) {
    int i = blockIdx.x * blockDim.x + threadIdx.x;   // float4 index
    if (i < MM * DD / 4) {
        float4 v = reinterpret_cast<const float4*>(x)[i];
        uint4 r;
        r.x = f2tf32(v.x); r.y = f2tf32(v.y);
        r.z = f2tf32(v.z); r.w = f2tf32(v.w);
        reinterpret_cast<uint4*>(g_xr)[i] = r;
    }
    if (i < DD * N3D / 4) {
        float4 v = reinterpret_cast<const float4*>(W)[i];
        uint4 r;
        r.x = f2tf32(v.x); r.y = f2tf32(v.y);
        r.z = f2tf32(v.z); r.w = f2tf32(v.w);
        reinterpret_cast<uint4*>(g_wr)[i] = r;
    }
}

// ---------------------------------------------------------------------------
// Kernel 1: qkv = xr @ wr + b via TF32 mma.sync, cp.async double-buffered.
// (unchanged from round 13 — measured ~170us)
// ---------------------------------------------------------------------------
__global__ __launch_bounds__(256, 2)
void qkv_mma_kernel(const float* __restrict__ bias) {
    __shared__ __align__(16) float sA[2][128 * 16];
    __shared__ __align__(16) float sB[2][16 * 128];

    const int tid  = threadIdx.x;
    const int lane = tid & 31;
    const int warp = tid >> 5;
    const int gid  = lane >> 2;
    const int tig  = lane & 3;
    const int warpM = (warp >> 2) * 64;
    const int warpN = (warp & 3) * 32;
    const int tileM = blockIdx.y * 128;
    const int tileN = blockIdx.x * 128;

    const int a_m0 = tid >> 2;
    const int a_kc = (tid & 3) * 4;
    const int b_k0 = tid >> 5;
    const int b_nc = (tid & 31) * 4;

    const uint32_t sAb = smem_u32(&sA[0][0]);
    const uint32_t sBb = smem_u32(&sB[0][0]);

    float acc[4][4][4];
#pragma unroll
    for (int mi = 0; mi < 4; mi++)
#pragma unroll
        for (int ni = 0; ni < 4; ni++)
#pragma unroll
            for (int c = 0; c < 4; c++) acc[mi][ni][c] = 0.0f;

#define ISSUE_TILE(t, s) do {                                                        \
        int _k0 = (t) * 16;                                                          \
        _Pragma("unroll")                                                            \
        for (int _i = 0; _i < 2; _i++) {                                             \
            int _m = a_m0 + _i * 64;                                                 \
            uint32_t _d = sAb + (uint32_t)((s) * 8192 +                              \
                          (_m * 16 + (a_kc ^ (4 * ((_m >> 1) & 3)))) * 4);           \
            cpasync16(_d, &g_xr[(size_t)(tileM + _m) * DD + _k0 + a_kc]);            \
        }                                                                            \
        _Pragma("unroll")                                                            \
        for (int _i = 0; _i < 2; _i++) {                                             \
            int _k = b_k0 + _i * 8;                                                  \
            uint32_t _d = sBb + (uint32_t)((s) * 8192 +                              \
                          (_k * 128 + (b_nc ^ (8 * (_k & 3)))) * 4);                 \
            cpasync16(_d, &g_wr[(size_t)(_k0 + _k) * N3D + tileN + b_nc]);           \
        }                                                                            \
        asm volatile("cp.async.commit_group;" ::: "memory");                         \
    } while (0)

    ISSUE_TILE(0, 0);

    const int swzA = 4 * ((gid >> 1) & 3);
    const int NT = DD / 16;
    for (int t = 0; t < NT; t++) {
        if (t + 1 < NT) {
            ISSUE_TILE(t + 1, (t + 1) & 1);
            asm volatile("cp.async.wait_group 1;" ::: "memory");
        } else {
            asm volatile("cp.async.wait_group 0;" ::: "memory");
        }
        __syncthreads();

        const float* A  = &sA[t & 1][0];
        const float* Bt = &sB[t & 1][0];
#pragma unroll
        for (int ks = 0; ks < 16; ks += 8) {
            uint32_t af[4][4];
            uint32_t bf[4][2];
#pragma unroll
            for (int mi = 0; mi < 4; mi++) {
                int m0 = warpM + mi * 16 + gid;
                int kA = ks + tig;
                af[mi][0] = __float_as_uint(A[m0 * 16       + (kA ^ swzA)]);
                af[mi][1] = __float_as_uint(A[(m0 + 8) * 16 + (kA ^ swzA)]);
                af[mi][2] = __float_as_uint(A[m0 * 16       + ((kA + 4) ^ swzA)]);
                af[mi][3] = __float_as_uint(A[(m0 + 8) * 16 + ((kA + 4) ^ swzA)]);
            }
#pragma unroll
            for (int ni = 0; ni < 4; ni++) {
                int n0 = warpN + ni * 8 + gid;
                bf[ni][0] = __float_as_uint(Bt[(ks + tig) * 128     + (n0 ^ (8 * tig))]);
                bf[ni][1] = __float_as_uint(Bt[(ks + tig + 4) * 128 + (n0 ^ (8 * tig))]);
            }
#pragma unroll
            for (int mi = 0; mi < 4; mi++)
#pragma unroll
                for (int ni = 0; ni < 4; ni++)
                    mma_tf32(acc[mi][ni][0], acc[mi][ni][1], acc[mi][ni][2], acc[mi][ni][3],
                             af[mi][0], af[mi][1], af[mi][2], af[mi][3],
                             bf[ni][0], bf[ni][1]);
        }
        __syncthreads();
    }
#undef ISSUE_TILE

#pragma unroll
    for (int mi = 0; mi < 4; mi++) {
#pragma unroll
        for (int ni = 0; ni < 4; ni++) {
            int row0 = tileM + warpM + mi * 16 + gid;
            int col0 = tileN + warpN + ni * 8 + tig * 2;
#pragma unroll
            for (int c = 0; c < 4; c++) {
                int m   = row0 + (c >> 1) * 8;
                int col = col0 + (c & 1);
                float val = acc[mi][ni][c] + bias[col];
                int b = m >> 10;
                int s = m & 1023;
                int h  = col / 192;
                int cc = col - h * 192;
                size_t base = ((size_t)(b * HH + h) * SS + s) * HD;
                if (cc < 64)       g_q[base + cc]       = val * 0.125f;
                else if (cc < 128) g_k[base + cc - 64]  = val;
                else               g_v[base + cc - 128] = val;
            }
        }
    }
}

// ---------------------------------------------------------------------------
// Kernel 2: flash-attention via TF32 mma.sync.
// Block = one (b,h) x 64 q-rows; 4 warps x 16 q-rows. 16 key tiles of 64.
//   SP: Qs then Ps [q][64], swizzle col ^ 4*(q&7)   (frag reads conflict-free)
//   Ks: [key][d],  swizzle d   ^ 4*(key&7)          (QK B-frag conflict-free)
//   Vs: [key][d],  swizzle d   ^ 8*(key&3)          (PV B-frag conflict-free)
// Scores/O in registers (c-layout rows gid/gid+8); online softmax with
// 4-lane butterfly reductions; Ps is warp-private (rows m0+gid, m0+gid+8).
// ---------------------------------------------------------------------------
__global__ __launch_bounds__(128)
void attn_mma_kernel(float* __restrict__ out) {
    __shared__ __align__(16) float SP[64 * 64];   // Qs, then reused as Ps
    __shared__ __align__(16) float Ks[64 * 64];
    __shared__ __align__(16) float Vs[64 * 64];

    const int tid  = threadIdx.x;
    const int lane = tid & 31;
    const int warp = tid >> 5;
    const int gid  = lane >> 2;      // 0..7
    const int tig  = lane & 3;       // 0..3
    const int m0   = warp * 16;
    const int bh   = blockIdx.x;     // 0..63
    const int q0   = blockIdx.y * 64;
    const int xq   = 4 * gid;        // XOR for SP/Ks fragment columns

    // Stage Q (swizzled), fully coalesced LDG
    const int sj = tid & 15;         // float4 within 64-float row
    const int sr = tid >> 4;         // + 8*p -> row 0..63
#pragma unroll
    for (int p = 0; p < 8; p++) {
        int row = sr + 8 * p;
        float4 qv = *reinterpret_cast<const float4*>(
            &g_q[((size_t)bh * SS + q0 + row) * HD + 4 * sj]);
        *reinterpret_cast<float4*>(&SP[row * 64 + ((4 * sj) ^ (4 * (row & 7)))]) = qv;
    }
    __syncthreads();

    // Q fragments for all 8 k-steps (32 regs), then SP is free for Ps
    uint32_t qf[8][4];
#pragma unroll
    for (int k8 = 0; k8 < 8; k8++) {
        int kk = k8 * 8;
        qf[k8][0] = __float_as_uint(SP[(m0 + gid) * 64     + ((kk + tig)     ^ xq)]);
        qf[k8][1] = __float_as_uint(SP[(m0 + gid + 8) * 64 + ((kk + tig)     ^ xq)]);
        qf[k8][2] = __float_as_uint(SP[(m0 + gid) * 64     + ((kk + tig + 4) ^ xq)]);
        qf[k8][3] = __float_as_uint(SP[(m0 + gid + 8) * 64 + ((kk + tig + 4) ^ xq)]);
    }

    float O[8][4];
#pragma unroll
    for (int nt = 0; nt < 8; nt++)
#pragma unroll
        for (int c = 0; c < 4; c++) O[nt][c] = 0.0f;
    float mA = -1e30f, mB = -1e30f, lA = 0.0f, lB = 0.0f;

    for (int kt = 0; kt < 16; kt++) {
        __syncthreads();   // prev PV done (and q-frags loaded, first iter)
        // Stage K and V tiles (swizzled)
#pragma unroll
        for (int p = 0; p < 8; p++) {
            int row = sr + 8 * p;
            size_t gb = ((size_t)bh * SS + kt * 64 + row) * HD + 4 * sj;
            float4 kv = *reinterpret_cast<const float4*>(&g_k[gb]);
            float4 vv = *reinterpret_cast<const float4*>(&g_v[gb]);
            *reinterpret_cast<float4*>(&Ks[row * 64 + ((4 * sj) ^ (4 * (row & 7)))]) = kv;
            *reinterpret_cast<float4*>(&Vs[row * 64 + ((4 * sj) ^ (8 * (row & 3)))]) = vv;
        }
        __syncthreads();

        // --- S = Q @ K^T : B[k=d][n=key] = Ks[key][d] ---
        float sc[8][4];
#pragma unroll
        for (int nt = 0; nt < 8; nt++)
#pragma unroll
            for (int c = 0; c < 4; c++) sc[nt][c] = 0.0f;
#pragma unroll
        for (int k8 = 0; k8 < 8; k8++) {
            int kk = k8 * 8;
#pragma unroll
            for (int nt = 0; nt < 8; nt++) {
                int n0 = nt * 8;
                uint32_t b0 = __float_as_uint(Ks[(n0 + gid) * 64 + ((kk + tig)     ^ xq)]);
                uint32_t b1 = __float_as_uint(Ks[(n0 + gid) * 64 + ((kk + tig + 4) ^ xq)]);
                mma_tf32(sc[nt][0], sc[nt][1], sc[nt][2], sc[nt][3],
                         qf[k8][0], qf[k8][1], qf[k8][2], qf[k8][3], b0, b1);
            }
        }

        // --- online softmax (rows A=gid, B=gid+8) ---
        float tA = -1e30f, tB = -1e30f;
#pragma unroll
        for (int nt = 0; nt < 8; nt++) {
            tA = fmaxf(tA, fmaxf(sc[nt][0], sc[nt][1]));
            tB = fmaxf(tB, fmaxf(sc[nt][2], sc[nt][3]));
        }
        tA = fmaxf(tA, __shfl_xor_sync(0xffffffffu, tA, 1));
        tA = fmaxf(tA, __shfl_xor_sync(0xffffffffu, tA, 2));
        tB = fmaxf(tB, __shfl_xor_sync(0xffffffffu, tB, 1));
        tB = fmaxf(tB, __shfl_xor_sync(0xffffffffu, tB, 2));
        float mnA = fmaxf(mA, tA), mnB = fmaxf(mB, tB);
        float cA = __expf(mA - mnA), cB = __expf(mB - mnB);
        mA = mnA; mB = mnB;

        float psA = 0.0f, psB = 0.0f;
#pragma unroll
        for (int nt = 0; nt < 8; nt++) {
            float p0 = __expf(sc[nt][0] - mA);
            float p1 = __expf(sc[nt][1] - mA);
            float p2 = __expf(sc[nt][2] - mB);
            float p3 = __expf(sc[nt][3] - mB);
            psA += p0 + p1; psB += p2 + p3;
            int colw = (nt * 8 + 2 * tig) ^ xq;   // XOR(mult of 4) keeps float2 aligned
            *reinterpret_cast<float2*>(&SP[(m0 + gid) * 64 + colw])     = make_float2(p0, p1);
            *reinterpret_cast<float2*>(&SP[(m0 + gid + 8) * 64 + colw]) = make_float2(p2, p3);
            O[nt][0] *= cA; O[nt][1] *= cA; O[nt][2] *= cB; O[nt][3] *= cB;
        }
        psA += __shfl_xor_sync(0xffffffffu, psA, 1);
        psA += __shfl_xor_sync(0xffffffffu, psA, 2);
        psB += __shfl_xor_sync(0xffffffffu, psB, 1);
        psB += __shfl_xor_sync(0xffffffffu, psB, 2);
        lA = lA * cA + psA;
        lB = lB * cB + psB;
        __syncwarp();   // Ps visible to all lanes of this warp

        // --- O += P @ V : A = Ps (warp-private rows), B[k=key][n=d] = Vs ---
#pragma unroll
        for (int k8 = 0; k8 < 8; k8++) {
            int kk = k8 * 8;
            uint32_t a0 = __float_as_uint(SP[(m0 + gid) * 64     + ((kk + tig)     ^ xq)]);
            uint32_t a1 = __float_as_uint(SP[(m0 + gid + 8) * 64 + ((kk + tig)     ^ xq)]);
            uint32_t a2 = __float_as_uint(SP[(m0 + gid) * 64     + ((kk + tig + 4) ^ xq)]);
            uint32_t a3 = __float_as_uint(SP[(m0 + gid + 8) * 64 + ((kk + tig + 4) ^ xq)]);
#pragma unroll
            for (int nt = 0; nt < 8; nt++) {
                uint32_t b0 = __float_as_uint(Vs[(kk + tig) * 64     + ((nt * 8 + gid) ^ (8 * tig))]);
                uint32_t b1 = __float_as_uint(Vs[(kk + tig + 4) * 64 + ((nt * 8 + gid) ^ (8 * tig))]);
                mma_tf32(O[nt][0], O[nt][1], O[nt][2], O[nt][3], a0, a1, a2, a3, b0, b1);
            }
        }
    }

    // Epilogue: out[b, q, h*64 + d]
    const int b = bh >> 4;
    const int h = bh & 15;
    float iA = 1.0f / lA, iB = 1.0f / lB;
    size_t rowA = ((size_t)b * SS + q0 + m0 + gid) * DD + h * HD;
    size_t rowB = rowA + (size_t)8 * DD;
#pragma unroll
    for (int nt = 0; nt < 8; nt++) {
        int col = nt * 8 + 2 * tig;
        *reinterpret_cast<float2*>(&out[rowA + col]) = make_float2(O[nt][0] * iA, O[nt][1] * iA);
        *reinterpret_cast<float2*>(&out[rowB + col]) = make_float2(O[nt][2] * iB, O[nt][3] * iB);
    }
}

extern "C" void kernel_launch(void* const* d_in, const int* in_sizes, int n_in,
                              void* d_out, int out_size) {
    const float* x  = (const float*)d_in[0];   // [B,S,D]
    const float* Wq = (const float*)d_in[1];   // [D,3D]
    const float* bq = (const float*)d_in[2];   // [3D]
    float* out      = (float*)d_out;           // [B,S,D]

    int np = MM * DD / 4;
    preround_kernel<<<(np + 255) / 256, 256>>>(x, Wq);

    dim3 gridG(N3D / 128, MM / 128);           // (24, 32)
    qkv_mma_kernel<<<gridG, 256>>>(bq);

    dim3 gridA(BB * HH, SS / 64);              // (64, 16)
    attn_mma_kernel<<<gridA, 128>>>(out);
}